// round 1
// baseline (speedup 1.0000x reference)
#include <cuda_runtime.h>

#define NB 512
#define NT 128
#define NH 8
#define NL 3

struct OS { float m, d, n; };

__device__ __forceinline__ OS os_combine(OS a, OS b) {
    float m  = fmaxf(a.m, b.m);
    float ea = __expf(a.m - m);
    float eb = __expf(b.m - m);
    OS r;
    r.m = m;
    r.d = a.d * ea + b.d * eb;
    r.n = a.n * ea + b.n * eb;
    return r;
}

__global__ __launch_bounds__(256) void cat_kernel(
    const float* __restrict__ X,
    const float* __restrict__ wk, const float* __restrict__ wq, const float* __restrict__ wv,
    const float* __restrict__ Wp, const float* __restrict__ bp,
    const float* __restrict__ W1, const float* __restrict__ b1,
    const float* __restrict__ W2, const float* __restrict__ b2,
    const float* __restrict__ w_lm, const float* __restrict__ b_lm,
    float* __restrict__ out)
{
    __shared__ float xs[NT];
    __shared__ float ho[NH][NT];

    const int b   = blockIdx.x;
    const int tid = threadIdx.x;
    const int h   = tid >> 5;   // warp id == head id
    const int lid = tid & 31;

    if (tid < NT) xs[tid] = X[b * NT + tid];
    __syncthreads();

    for (int l = 0; l < NL; ++l) {
        // ---- per-head exclusive prefix online-softmax scan over T=128 ----
        {
            const float c   = wk[l * NH + h] * wq[l * NH + h];
            const float wvh = wv[l * NH + h];
            const int   t0  = lid * 4;

            // vectorized shared read (conflict-free)
            float4 xv4 = reinterpret_cast<const float4*>(xs)[lid];

            OS e0 = { c * xv4.x * xv4.x, 1.0f, wvh * xv4.x };
            OS e1 = { c * xv4.y * xv4.y, 1.0f, wvh * xv4.y };
            OS e2 = { c * xv4.z * xv4.z, 1.0f, wvh * xv4.z };
            OS e3 = { c * xv4.w * xv4.w, 1.0f, wvh * xv4.w };

            // local inclusive aggregates within lane
            OS a0 = e0;
            OS a1 = os_combine(a0, e1);
            OS a2 = os_combine(a1, e2);
            OS a3 = os_combine(a2, e3);

            // warp inclusive scan of lane totals
            OS agg = a3;
            #pragma unroll
            for (int ofs = 1; ofs < 32; ofs <<= 1) {
                OS up;
                up.m = __shfl_up_sync(0xffffffffu, agg.m, ofs);
                up.d = __shfl_up_sync(0xffffffffu, agg.d, ofs);
                up.n = __shfl_up_sync(0xffffffffu, agg.n, ofs);
                if (lid >= ofs) agg = os_combine(up, agg);
            }
            // exclusive prefix entering this lane
            OS P;
            P.m = __shfl_up_sync(0xffffffffu, agg.m, 1);
            P.d = __shfl_up_sync(0xffffffffu, agg.d, 1);
            P.n = __shfl_up_sync(0xffffffffu, agg.n, 1);
            if (lid == 0) { P.m = -1e30f; P.d = 0.0f; P.n = 0.0f; }

            // per-element exclusive aggregates
            OS x0e = P;
            OS x1e = os_combine(P, a0);
            OS x2e = os_combine(P, a1);
            OS x3e = os_combine(P, a2);

            ho[h][t0 + 0] = (x0e.d > 0.0f) ? x0e.n / x0e.d : 0.0f;
            ho[h][t0 + 1] = (x1e.d > 0.0f) ? x1e.n / x1e.d : 0.0f;
            ho[h][t0 + 2] = (x2e.d > 0.0f) ? x2e.n / x2e.d : 0.0f;
            ho[h][t0 + 3] = (x3e.d > 0.0f) ? x3e.n / x3e.d : 0.0f;
        }
        __syncthreads();

        // ---- output projection + FF (scalar per t), threads 0..127 ----
        if (tid < NT) {
            float y = bp[l];
            #pragma unroll
            for (int hh = 0; hh < NH; ++hh) y += ho[hh][tid] * Wp[l * NH + hh];
            float f = b2[l];
            #pragma unroll
            for (int k = 0; k < 4; ++k) {
                float h1 = fmaxf(fmaf(y, W1[l * 4 + k], b1[l * 4 + k]), 0.0f);
                f = fmaf(h1, W2[l * 4 + k], f);
            }
            xs[tid] = y + f;
        }
        __syncthreads();
    }

    if (tid < NT) out[b * NT + tid] = fmaf(xs[tid], w_lm[0], b_lm[0]);
}

extern "C" void kernel_launch(void* const* d_in, const int* in_sizes, int n_in,
                              void* d_out, int out_size) {
    (void)in_sizes; (void)n_in; (void)out_size;
    cat_kernel<<<NB, 256>>>(
        (const float*)d_in[0],  // X
        (const float*)d_in[1],  // wk
        (const float*)d_in[2],  // wq
        (const float*)d_in[3],  // wv
        (const float*)d_in[4],  // Wp
        (const float*)d_in[5],  // bp
        (const float*)d_in[6],  // W1
        (const float*)d_in[7],  // b1
        (const float*)d_in[8],  // W2
        (const float*)d_in[9],  // b2
        (const float*)d_in[10], // w_lm
        (const float*)d_in[11], // b_lm
        (float*)d_out);
}

// round 2
// speedup vs baseline: 1.1914x; 1.1914x over previous
#include <cuda_runtime.h>

#define NB 512
#define NT 128
#define NH 8
#define NL 3
#define LOG2E 1.4426950408889634f

// weight cache offsets in shared
#define O_WK  0
#define O_WQ  24
#define O_WV  48
#define O_WP  72
#define O_BP  96
#define O_W1  99
#define O_B1  111
#define O_W2  123
#define O_B2  135
#define O_WLM 138
#define O_BLM 139
#define NWTS  140

struct OS { float m, d, n; };

__device__ __forceinline__ float ex2(float x) {
    float y;
    asm("ex2.approx.ftz.f32 %0, %1;" : "=f"(y) : "f"(x));
    return y;
}

// online-softmax monoid combine, single exp (scores pre-scaled by log2e)
__device__ __forceinline__ OS comb(OS a, OS b) {
    float mx = fmaxf(a.m, b.m);
    float mn = fminf(a.m, b.m);
    float e  = ex2(mn - mx);
    bool  bl = a.m < b.m;       // a is the smaller side -> scale a
    float sa = bl ? e : 1.0f;
    float sb = bl ? 1.0f : e;
    OS r;
    r.m = mx;
    r.d = fmaf(a.d, sa, b.d * sb);
    r.n = fmaf(a.n, sa, b.n * sb);
    return r;
}

__global__ __launch_bounds__(256) void cat_kernel(
    const float* __restrict__ X,
    const float* __restrict__ wk, const float* __restrict__ wq, const float* __restrict__ wv,
    const float* __restrict__ Wp, const float* __restrict__ bp,
    const float* __restrict__ W1, const float* __restrict__ b1,
    const float* __restrict__ W2, const float* __restrict__ b2,
    const float* __restrict__ w_lm, const float* __restrict__ b_lm,
    float* __restrict__ out)
{
    __shared__ float xs[NT];
    __shared__ float ho[NH][NT];
    __shared__ float W[NWTS];

    const int b   = blockIdx.x;
    const int tid = threadIdx.x;
    const int h   = tid >> 5;   // warp id == head id
    const int lid = tid & 31;

    // ---- one-time weight preload into shared (parallel, overlapped) ----
    {
        int i = tid;
        if      (i < 24)  W[i] = wk[i];
        else if (i < 48)  W[i] = wq[i - 24];
        else if (i < 72)  W[i] = wv[i - 48];
        else if (i < 96)  W[i] = Wp[i - 72];
        else if (i < 99)  W[i] = bp[i - 96];
        else if (i < 111) W[i] = W1[i - 99];
        else if (i < 123) W[i] = b1[i - 111];
        else if (i < 135) W[i] = W2[i - 123];
        else if (i < 138) W[i] = b2[i - 135];
        else if (i == 138) W[i] = w_lm[0];
        else if (i == 139) W[i] = b_lm[0];
    }
    if (tid < NT) xs[tid] = X[b * NT + tid];
    __syncthreads();

    // per-head scan weights for all layers (registers)
    float cl0 = W[O_WK + 0*NH + h] * W[O_WQ + 0*NH + h] * LOG2E;
    float cl1 = W[O_WK + 1*NH + h] * W[O_WQ + 1*NH + h] * LOG2E;
    float cl2 = W[O_WK + 2*NH + h] * W[O_WQ + 2*NH + h] * LOG2E;
    float wv0 = W[O_WV + 0*NH + h];
    float wv1 = W[O_WV + 1*NH + h];
    float wv2 = W[O_WV + 2*NH + h];

    #pragma unroll
    for (int l = 0; l < NL; ++l) {
        const float c   = (l == 0) ? cl0 : (l == 1) ? cl1 : cl2;
        const float wvh = (l == 0) ? wv0 : (l == 1) ? wv1 : wv2;

        // ---- per-head exclusive prefix online-softmax scan over T=128 ----
        {
            const int t0 = lid * 4;
            float4 xv4 = reinterpret_cast<const float4*>(xs)[lid];

            OS e0 = { c * xv4.x * xv4.x, 1.0f, wvh * xv4.x };
            OS e1 = { c * xv4.y * xv4.y, 1.0f, wvh * xv4.y };
            OS e2 = { c * xv4.z * xv4.z, 1.0f, wvh * xv4.z };
            OS e3 = { c * xv4.w * xv4.w, 1.0f, wvh * xv4.w };

            // local inclusive aggregates
            OS a0 = e0;
            OS a1 = comb(a0, e1);
            OS a2 = comb(a1, e2);
            OS a3 = comb(a2, e3);

            // warp inclusive scan of lane totals
            OS agg = a3;
            #pragma unroll
            for (int ofs = 1; ofs < 32; ofs <<= 1) {
                OS up;
                up.m = __shfl_up_sync(0xffffffffu, agg.m, ofs);
                up.d = __shfl_up_sync(0xffffffffu, agg.d, ofs);
                up.n = __shfl_up_sync(0xffffffffu, agg.n, ofs);
                if (lid >= ofs) agg = comb(up, agg);
            }
            // exclusive prefix entering this lane
            OS P;
            P.m = __shfl_up_sync(0xffffffffu, agg.m, 1);
            P.d = __shfl_up_sync(0xffffffffu, agg.d, 1);
            P.n = __shfl_up_sync(0xffffffffu, agg.n, 1);
            if (lid == 0) { P.m = -1e30f; P.d = 0.0f; P.n = 0.0f; }

            // per-element exclusive aggregates (d >= 1 whenever prefix non-empty)
            OS x1e = comb(P, a0);
            OS x2e = comb(P, a1);
            OS x3e = comb(P, a2);

            ho[h][t0 + 0] = (P.d   > 0.0f) ? __fdividef(P.n,   P.d)   : 0.0f;
            ho[h][t0 + 1] = __fdividef(x1e.n, x1e.d);
            ho[h][t0 + 2] = __fdividef(x2e.n, x2e.d);
            ho[h][t0 + 3] = __fdividef(x3e.n, x3e.d);
        }
        __syncthreads();

        // ---- output projection + FF (scalar per t), threads 0..127 ----
        if (tid < NT) {
            float y = W[O_BP + l];
            #pragma unroll
            for (int hh = 0; hh < NH; ++hh) y = fmaf(ho[hh][tid], W[O_WP + l*NH + hh], y);
            float f = W[O_B2 + l];
            #pragma unroll
            for (int k = 0; k < 4; ++k) {
                float h1 = fmaxf(fmaf(y, W[O_W1 + l*4 + k], W[O_B1 + l*4 + k]), 0.0f);
                f = fmaf(h1, W[O_W2 + l*4 + k], f);
            }
            float xn = y + f;
            if (l == NL - 1) {
                out[b * NT + tid] = fmaf(xn, W[O_WLM], W[O_BLM]);
            } else {
                xs[tid] = xn;
            }
        }
        if (l < NL - 1) __syncthreads();
    }
}

extern "C" void kernel_launch(void* const* d_in, const int* in_sizes, int n_in,
                              void* d_out, int out_size) {
    (void)in_sizes; (void)n_in; (void)out_size;
    cat_kernel<<<NB, 256>>>(
        (const float*)d_in[0],  // X
        (const float*)d_in[1],  // wk
        (const float*)d_in[2],  // wq
        (const float*)d_in[3],  // wv
        (const float*)d_in[4],  // Wp
        (const float*)d_in[5],  // bp
        (const float*)d_in[6],  // W1
        (const float*)d_in[7],  // b1
        (const float*)d_in[8],  // W2
        (const float*)d_in[9],  // b2
        (const float*)d_in[10], // w_lm
        (const float*)d_in[11], // b_lm
        (float*)d_out);
}